// round 8
// baseline (speedup 1.0000x reference)
#include <cuda_runtime.h>
#include <cstdint>

#define B_    8
#define F_IN  32
#define CN    256
#define M_    64
#define C_OUT 64
#define C_CAT 224   // (2*3+1)*32
#define KC    16
#define WS_STRIDE 68

// Scratch: H[b][m][fc][c], fc in [0,224): piece p at fc=32p.
__device__ float g_H[(size_t)B_ * M_ * C_CAT * CN];

// ================= shared helpers =================
__device__ __forceinline__ uint32_t smem_u32(const void* p) {
    uint32_t a;
    asm("{ .reg .u64 t; cvta.to.shared.u64 t, %1; cvt.u32.u64 %0, t; }" : "=r"(a) : "l"(p));
    return a;
}
__device__ __forceinline__ void cp_async16(uint32_t sa, const void* g) {
    asm volatile("cp.async.cg.shared.global [%0], [%1], 16;\n" :: "r"(sa), "l"(g));
}
__device__ __forceinline__ void cp_commit() { asm volatile("cp.async.commit_group;\n"); }
template<int N> __device__ __forceinline__ void cp_wait() {
    asm volatile("cp.async.wait_group %0;\n" :: "n"(N));
}

// packed f32x2 helpers (k_final)
__device__ __forceinline__ uint64_t pk2(float lo, float hi) {
    uint64_t r; asm("mov.b64 %0,{%1,%2};" : "=l"(r) : "f"(lo), "f"(hi)); return r;
}
__device__ __forceinline__ void upk2(uint64_t p, float& lo, float& hi) {
    asm("mov.b64 {%0,%1},%2;" : "=f"(lo), "=f"(hi) : "l"(p));
}
__device__ __forceinline__ void ffma2(uint64_t& d, uint64_t a, uint64_t b) {
    asm("fma.rn.f32x2 %0,%1,%2,%0;" : "+l"(d) : "l"(a), "l"(b));
}

// truncation split: (a0,a1) -> hi2 = {trunc16(a1),trunc16(a0)} via PRMT, lo2 = rn-bf16 residuals
__device__ __forceinline__ void split2t(float a0, float a1, uint32_t& hi2, uint32_t& lo2) {
    uint32_t ra0 = __float_as_uint(a0), ra1 = __float_as_uint(a1);
    asm("prmt.b32 %0, %1, %2, 0x7632;" : "=r"(hi2) : "r"(ra0), "r"(ra1));
    float h0 = __uint_as_float(ra0 & 0xFFFF0000u);
    float h1 = __uint_as_float(ra1 & 0xFFFF0000u);
    float l0 = a0 - h0, l1 = a1 - h1;
    asm("cvt.rn.bf16x2.f32 %0, %1, %2;" : "=r"(lo2) : "f"(l1), "f"(l0));
}

// ldmatrix x4 (non-trans)
__device__ __forceinline__ void ldsm4(uint32_t r[4], uint32_t addr) {
    asm volatile("ldmatrix.sync.aligned.m8n8.x4.shared.b16 {%0,%1,%2,%3}, [%4];"
                 : "=r"(r[0]), "=r"(r[1]), "=r"(r[2]), "=r"(r[3]) : "r"(addr));
}
// mma m16n8k16 row.col bf16 -> f32
__device__ __forceinline__ void mma16816(float c[4], const uint32_t a[4],
                                         uint32_t b0, uint32_t b1) {
    asm volatile("mma.sync.aligned.m16n8k16.row.col.f32.bf16.bf16.f32 "
                 "{%0,%1,%2,%3},{%4,%5,%6,%7},{%8,%9},{%0,%1,%2,%3};"
                 : "+f"(c[0]), "+f"(c[1]), "+f"(c[2]), "+f"(c[3])
                 : "r"(a[0]), "r"(a[1]), "r"(a[2]), "r"(a[3]), "r"(b0), "r"(b1));
}

// ================= Kernel 1: x[b,f,n,m] -> H[b][m][0..31][n] =================
__global__ __launch_bounds__(256) void k_transpose(const float* __restrict__ x) {
    int id = blockIdx.x;           // ((b*32 + f)*8 + nt)
    int nt = id & 7;
    int f  = (id >> 3) & 31;
    int b  = id >> 8;

    __shared__ float ts[32][65];
    int t  = threadIdx.x;
    int m  = t & 63;
    int nl = t >> 6;               // 0..3
    const float* xp = x + ((size_t)(b * F_IN + f) * CN + nt * 32) * M_;
#pragma unroll
    for (int i = 0; i < 8; ++i) {
        int r = nl + 4 * i;
        ts[r][m] = xp[(size_t)r * M_ + m];
    }
    __syncthreads();
    int nl2 = t & 31;
    int mg  = t >> 5;              // 0..7
#pragma unroll
    for (int i = 0; i < 8; ++i) {
        int mm = mg + 8 * i;
        g_H[((size_t)(b * M_ + mm) * C_CAT + f) * CN + nt * 32 + nl2] = ts[nl2][mm];
    }
}

// ================= Kernel 2: HMMA fused double-hop nconv (pipelined) =================
// One CTA per (base, b, m). D[v(256) x f(32)] = sum_n A[n][v] * x[f][n]
// mma m16n8k16 bf16, fp32 accum, 3-term truncation split.
//
// smem (bytes):
//   xs hi/lo:   [f=32][np=128] words, stride 132     -> 2 * 16896
//   As hi/lo:   [v=256][8 np] stride 20, G-swizzled  -> 2 * 20480 (single buffer)
//   stg:        2 x [n=16][260] fp32 staging         -> 2 * 16640
#define AS_STR 20
#define XS_STR 132
#define SM_XS_HI 0u
#define SM_XS_LO 16896u
#define SM_AS_HI 33792u
#define SM_AS_LO 54272u
#define SM_STG   74752u
#define STG_BUF  16640u
#define STG_ROWF 260
#define SM_X1    33792u          // fp32 [256][33] (33792 B), aliases As region
#define SM_TOT   108032u

// As word offset with group swizzle: G' = (j>>2) ^ ((v>>3)&1)
__device__ __forceinline__ uint32_t as_word(int v, int j) {
    return (uint32_t)(v * AS_STR + 4 * (((j >> 2) ^ ((v >> 3) & 1))) + (j & 3));
}

__global__ __launch_bounds__(256, 2) void k_nconv(const float* __restrict__ b0,
                                                  const float* __restrict__ b1,
                                                  const float* __restrict__ b2)
{
    extern __shared__ char smem[];
    uint32_t sb = smem_u32(smem);
    int t   = threadIdx.x;
    int wid = t >> 5;
    int l   = t & 31;

    int id = blockIdx.x;                    // 0..1535
    int kb = id >> 9;
    int bm = id & 511;
    const float* Ag = (kb == 0 ? b0 : (kb == 1 ? b1 : b2)) + (size_t)bm * (CN * CN);
    float* Hbm = g_H + (size_t)bm * (C_CAT * CN);

    // staging cp.async lane assignment: thread covers rows n = 4k + (t>>6), 16B at col (t&63)*4
    int srow = t >> 6;
    int scol = (t & 63) * 4;

    // ---- prologue: stage chunk 0 ----
#pragma unroll
    for (int k = 0; k < 4; ++k) {
        int n = 4 * k + srow;
        cp_async16(sb + SM_STG + (uint32_t)(n * STG_ROWF + scol) * 4u,
                   Ag + (size_t)n * CN + scol);
    }
    cp_commit();

    // ---- build xs (hi/lo) from piece 0 [f][n] fp32 ----
    {
        const float2* src = (const float2*)Hbm;
#pragma unroll
        for (int k = 0; k < 16; ++k) {
            int pos = t + 256 * k;          // f = pos>>7, np = pos&127
            int f = pos >> 7, np = pos & 127;
            float2 a = src[pos];
            uint32_t hi2, lo2; split2t(a.x, a.y, hi2, lo2);
            uint32_t off = (uint32_t)(f * XS_STR + np) * 4u;
            *(uint32_t*)(smem + SM_XS_HI + off) = hi2;
            *(uint32_t*)(smem + SM_XS_LO + off) = lo2;
        }
    }

    // ---- per-lane ldmatrix addresses ----
    int sub  = l >> 3;                      // 0..3
    int arow = (l & 7) + 8 * (sub & 1);
    int anpA = 4 * ((sub >> 1) ^ (sub & 1));    // swizzled A group
    int anpX = 4 * (sub >> 1);                  // x side unswizzled
    uint32_t aA  = sb + SM_AS_HI + (uint32_t)((32 * wid + arow) * AS_STR + anpA) * 4u;
    uint32_t aX0 = sb + SM_XS_HI + (uint32_t)(arow * XS_STR + anpX) * 4u;
    uint32_t aX1 = sb + SM_XS_HI + (uint32_t)((16 + arow) * XS_STR + anpX) * 4u;
    const uint32_t ALO = SM_AS_LO - SM_AS_HI;   // 20480
    const uint32_t XLO = SM_XS_LO - SM_XS_HI;   // 16896

    int grp = l >> 2, qp = l & 3;

    __syncthreads();

    for (int h = 0; h < 2; ++h) {
        float acc[2][4][4];
#pragma unroll
        for (int mt = 0; mt < 2; ++mt)
#pragma unroll
            for (int nt = 0; nt < 4; ++nt)
#pragma unroll
                for (int e = 0; e < 4; ++e) acc[mt][nt][e] = 0.0f;

        for (int c = 0; c < 16; ++c) {
            // stage next chunk (always commit to keep group counting uniform)
            bool issue = (h == 0) || (c < 15);
            if (issue) {
                int nc = (c + 1) & 15;      // h0,c=15 -> prefetch hop2 chunk 0 (L2)
                const float* src = Ag + (size_t)nc * 16 * CN;
                uint32_t dst = sb + SM_STG + ((c + 1) & 1) * STG_BUF;
#pragma unroll
                for (int k = 0; k < 4; ++k) {
                    int n = 4 * k + srow;
                    cp_async16(dst + (uint32_t)(n * STG_ROWF + scol) * 4u,
                               src + (size_t)n * CN + scol);
                }
            }
            cp_commit();
            cp_wait<1>();                   // chunk c staged
            __syncthreads();                // + all warps done MMA(c-1) reading As

            // convert stg[c&1] -> As hi/lo (thread = column v = t)
            {
                const float* stg = (const float*)(smem + SM_STG + (c & 1) * STG_BUF);
#pragma unroll
                for (int j = 0; j < 8; ++j) {
                    float a0 = stg[(2 * j) * STG_ROWF + t];
                    float a1 = stg[(2 * j + 1) * STG_ROWF + t];
                    uint32_t hi2, lo2; split2t(a0, a1, hi2, lo2);
                    uint32_t w = as_word(t, j) * 4u;
                    *(uint32_t*)(smem + SM_AS_HI + w) = hi2;
                    *(uint32_t*)(smem + SM_AS_LO + w) = lo2;
                }
            }
            __syncthreads();

            // MMA: one k16 step over this chunk
            {
                uint32_t npg = 8u * c;      // x word offset for this chunk
                uint32_t aH[2][4], aL[2][4], xH[2][4], xL[2][4];
                ldsm4(aH[0], aA);
                ldsm4(aH[1], aA + (16u * AS_STR) * 4u);
                ldsm4(aL[0], aA + ALO);
                ldsm4(aL[1], aA + ALO + (16u * AS_STR) * 4u);
                ldsm4(xH[0], aX0 + npg * 4u);
                ldsm4(xH[1], aX1 + npg * 4u);
                ldsm4(xL[0], aX0 + XLO + npg * 4u);
                ldsm4(xL[1], aX1 + XLO + npg * 4u);
#pragma unroll
                for (int mt = 0; mt < 2; ++mt)
#pragma unroll
                    for (int fb = 0; fb < 2; ++fb) {
                        mma16816(acc[mt][2 * fb],     aH[mt], xH[fb][0], xH[fb][2]);
                        mma16816(acc[mt][2 * fb + 1], aH[mt], xH[fb][1], xH[fb][3]);
                        mma16816(acc[mt][2 * fb],     aL[mt], xH[fb][0], xH[fb][2]);
                        mma16816(acc[mt][2 * fb + 1], aL[mt], xH[fb][1], xH[fb][3]);
                        mma16816(acc[mt][2 * fb],     aH[mt], xL[fb][0], xL[fb][2]);
                        mma16816(acc[mt][2 * fb + 1], aH[mt], xL[fb][1], xL[fb][3]);
                    }
            }
        }

        __syncthreads();   // all MMAs done (As/x1s alias safety)

        // ---- epilogue: write piece to global; (h==0) rebuild xs from result ----
        int piece = 1 + 2 * kb + h;
        float* Hp = Hbm + (size_t)(32 * piece) * CN;
#pragma unroll
        for (int mt = 0; mt < 2; ++mt)
#pragma unroll
            for (int nt = 0; nt < 4; ++nt) {
                int v0 = 32 * wid + 16 * mt + grp;
                int f0 = 8 * nt + 2 * qp;
                Hp[(size_t)f0 * CN + v0]           = acc[mt][nt][0];
                Hp[(size_t)(f0 + 1) * CN + v0]     = acc[mt][nt][1];
                Hp[(size_t)f0 * CN + v0 + 8]       = acc[mt][nt][2];
                Hp[(size_t)(f0 + 1) * CN + v0 + 8] = acc[mt][nt][3];
            }

        if (h == 0) {
            float* x1s = (float*)(smem + SM_X1);    // aliases As (idle now)
#pragma unroll
            for (int mt = 0; mt < 2; ++mt)
#pragma unroll
                for (int nt = 0; nt < 4; ++nt) {
                    int v0 = 32 * wid + 16 * mt + grp;
                    int f0 = 8 * nt + 2 * qp;
                    x1s[v0 * 33 + f0]           = acc[mt][nt][0];
                    x1s[v0 * 33 + f0 + 1]       = acc[mt][nt][1];
                    x1s[(v0 + 8) * 33 + f0]     = acc[mt][nt][2];
                    x1s[(v0 + 8) * 33 + f0 + 1] = acc[mt][nt][3];
                }
            __syncthreads();
            // xs[f][n=v] <- x1s[v][f]
            int f = t & 31, g8 = t >> 5;
#pragma unroll
            for (int k = 0; k < 16; ++k) {
                int np = g8 + 8 * k;
                float a0 = x1s[(2 * np) * 33 + f];
                float a1 = x1s[(2 * np + 1) * 33 + f];
                uint32_t hi2, lo2; split2t(a0, a1, hi2, lo2);
                uint32_t off = (uint32_t)(f * XS_STR + np) * 4u;
                *(uint32_t*)(smem + SM_XS_HI + off) = hi2;
                *(uint32_t*)(smem + SM_XS_LO + off) = lo2;
            }
            __syncthreads();
        }
    }
}

// ================= Kernel 3: y[b,o,c,m] = W[o,:] . H[b][m][:][c] + bias[o] =================
__global__ __launch_bounds__(256, 2) void k_final(const float* __restrict__ W,
                                                  const float* __restrict__ bias,
                                                  float* __restrict__ y)
{
    extern __shared__ float smemf[];
    float* Ws = smemf;                      // 224*68 transposed W: Ws[fc][o]
    float* Hs = Ws + C_CAT * WS_STRIDE;     // 2*KC*256

    int bm = blockIdx.x;
    int b  = bm >> 6;
    int m  = bm & 63;
    const float* Hbm = g_H + (size_t)bm * (C_CAT * CN);

    int t  = threadIdx.x;
    int tv = t & 31;
    int og = t >> 5;                        // 0..7

    int lr = t >> 6;
    int lc = (t & 63) * 4;

#pragma unroll
    for (int r = 0; r < 4; ++r)
        cp_async16(smem_u32(&Hs[(lr + 4 * r) * CN + lc]), Hbm + (size_t)(lr + 4 * r) * CN + lc);
    cp_commit();

    for (int i = t; i < C_OUT * C_CAT; i += 256) {
        int o = i / C_CAT, fc = i % C_CAT;
        Ws[fc * WS_STRIDE + o] = W[i];
    }
    float bv[8];
#pragma unroll
    for (int i = 0; i < 8; ++i) bv[i] = bias[8 * og + i];

    uint64_t acc2[4][2][4];
#pragma unroll
    for (int p = 0; p < 4; ++p)
#pragma unroll
        for (int q = 0; q < 2; ++q)
#pragma unroll
            for (int j = 0; j < 4; ++j) acc2[p][q][j] = 0ull;

    const int NCH = C_CAT / KC;  // 14
    for (int ch = 0; ch < NCH; ++ch) {
        float* buf = Hs + (ch & 1) * (KC * CN);
        if (ch < NCH - 1) {
            float* nbuf = Hs + ((ch + 1) & 1) * (KC * CN);
            const float* Hc = Hbm + (size_t)(ch + 1) * KC * CN;
#pragma unroll
            for (int r = 0; r < 4; ++r)
                cp_async16(smem_u32(&nbuf[(lr + 4 * r) * CN + lc]), Hc + (size_t)(lr + 4 * r) * CN + lc);
            cp_commit();
            cp_wait<1>();
        } else {
            cp_wait<0>();
        }
        __syncthreads();
#pragma unroll
        for (int kk = 0; kk < KC; ++kk) {
            float4 w0 = *(const float4*)&Ws[(ch * KC + kk) * WS_STRIDE + 8 * og];
            float4 w1 = *(const float4*)&Ws[(ch * KC + kk) * WS_STRIDE + 8 * og + 4];
            float4 h0 = *(const float4*)&buf[kk * CN + 4 * tv];
            float4 h1 = *(const float4*)&buf[kk * CN + 128 + 4 * tv];
            uint64_t wp[4] = { pk2(w0.x, w0.y), pk2(w0.z, w0.w),
                               pk2(w1.x, w1.y), pk2(w1.z, w1.w) };
            uint64_t hd[2][4] = {
                { pk2(h0.x, h0.x), pk2(h0.y, h0.y), pk2(h0.z, h0.z), pk2(h0.w, h0.w) },
                { pk2(h1.x, h1.x), pk2(h1.y, h1.y), pk2(h1.z, h1.z), pk2(h1.w, h1.w) }
            };
#pragma unroll
            for (int p = 0; p < 4; ++p)
#pragma unroll
                for (int q = 0; q < 2; ++q)
#pragma unroll
                    for (int j = 0; j < 4; ++j)
                        ffma2(acc2[p][q][j], wp[p], hd[q][j]);
        }
        __syncthreads();
    }

#pragma unroll
    for (int p = 0; p < 4; ++p) {
#pragma unroll
        for (int q = 0; q < 2; ++q)
#pragma unroll
            for (int j = 0; j < 4; ++j) {
                float lo, hi;
                upk2(acc2[p][q][j], lo, hi);
                int o0 = 8 * og + 2 * p;
                int c  = 128 * q + 4 * tv + j;
                size_t ob0 = ((size_t)(b * C_OUT + o0) * CN + c) * M_ + m;
                size_t ob1 = ((size_t)(b * C_OUT + o0 + 1) * CN + c) * M_ + m;
                y[ob0] = lo + bv[2 * p];
                y[ob1] = hi + bv[2 * p + 1];
            }
    }
}

// ================= launch =================
extern "C" void kernel_launch(void* const* d_in, const int* in_sizes, int n_in,
                              void* d_out, int out_size) {
    const float* x    = (const float*)d_in[0];
    const float* b0   = (const float*)d_in[1];
    const float* b1   = (const float*)d_in[2];
    const float* b2   = (const float*)d_in[3];
    const float* W    = (const float*)d_in[4];
    const float* bias = (const float*)d_in[5];
    float* y = (float*)d_out;

    const int SMEM_K3 = (C_CAT * WS_STRIDE + 2 * KC * CN) * 4;     // 93,696 B
    cudaFuncSetAttribute(k_nconv, cudaFuncAttributeMaxDynamicSharedMemorySize, (int)SM_TOT);
    cudaFuncSetAttribute(k_final, cudaFuncAttributeMaxDynamicSharedMemorySize, SMEM_K3);

    k_transpose<<<2048, 256>>>(x);
    k_nconv<<<1536, 256, SM_TOT>>>(b0, b1, b2);
    k_final<<<512, 256, SMEM_K3>>>(W, bias, y);
}

// round 9
// speedup vs baseline: 1.2368x; 1.2368x over previous
#include <cuda_runtime.h>
#include <cstdint>

#define B_    8
#define F_IN  32
#define CN    256
#define M_    64
#define C_OUT 64
#define C_CAT 224   // (2*3+1)*32
#define KC    16
#define WS_STRIDE 68

// Scratch: H[b][m][fc][c], fc in [0,224): piece p at fc=32p.
__device__ float g_H[(size_t)B_ * M_ * C_CAT * CN];

// ================= shared helpers =================
__device__ __forceinline__ uint32_t smem_u32(const void* p) {
    uint32_t a;
    asm("{ .reg .u64 t; cvta.to.shared.u64 t, %1; cvt.u32.u64 %0, t; }" : "=r"(a) : "l"(p));
    return a;
}
__device__ __forceinline__ void cp_async16(uint32_t sa, const void* g) {
    asm volatile("cp.async.cg.shared.global [%0], [%1], 16;\n" :: "r"(sa), "l"(g));
}
__device__ __forceinline__ void cp_commit() { asm volatile("cp.async.commit_group;\n"); }
template<int N> __device__ __forceinline__ void cp_wait() {
    asm volatile("cp.async.wait_group %0;\n" :: "n"(N));
}

// packed f32x2 helpers (k_final)
__device__ __forceinline__ uint64_t pk2(float lo, float hi) {
    uint64_t r; asm("mov.b64 %0,{%1,%2};" : "=l"(r) : "f"(lo), "f"(hi)); return r;
}
__device__ __forceinline__ void upk2(uint64_t p, float& lo, float& hi) {
    asm("mov.b64 {%0,%1},%2;" : "=f"(lo), "=f"(hi) : "l"(p));
}
__device__ __forceinline__ void ffma2(uint64_t& d, uint64_t a, uint64_t b) {
    asm("fma.rn.f32x2 %0,%1,%2,%0;" : "+l"(d) : "l"(a), "l"(b));
}

// truncation split: (a0,a1) -> hi2 = {trunc16(a1),trunc16(a0)} via PRMT, lo2 = rn-bf16 residuals
__device__ __forceinline__ void split2t(float a0, float a1, uint32_t& hi2, uint32_t& lo2) {
    uint32_t ra0 = __float_as_uint(a0), ra1 = __float_as_uint(a1);
    asm("prmt.b32 %0, %1, %2, 0x7632;" : "=r"(hi2) : "r"(ra0), "r"(ra1));
    float h0 = __uint_as_float(ra0 & 0xFFFF0000u);
    float h1 = __uint_as_float(ra1 & 0xFFFF0000u);
    float l0 = a0 - h0, l1 = a1 - h1;
    asm("cvt.rn.bf16x2.f32 %0, %1, %2;" : "=r"(lo2) : "f"(l1), "f"(l0));
}

// ldmatrix x4 (non-trans)
__device__ __forceinline__ void ldsm4(uint32_t r[4], uint32_t addr) {
    asm volatile("ldmatrix.sync.aligned.m8n8.x4.shared.b16 {%0,%1,%2,%3}, [%4];"
                 : "=r"(r[0]), "=r"(r[1]), "=r"(r[2]), "=r"(r[3]) : "r"(addr));
}
// mma m16n8k16 row.col bf16 -> f32
__device__ __forceinline__ void mma16816(float c[4], const uint32_t a[4],
                                         uint32_t b0, uint32_t b1) {
    asm volatile("mma.sync.aligned.m16n8k16.row.col.f32.bf16.bf16.f32 "
                 "{%0,%1,%2,%3},{%4,%5,%6,%7},{%8,%9},{%0,%1,%2,%3};"
                 : "+f"(c[0]), "+f"(c[1]), "+f"(c[2]), "+f"(c[3])
                 : "r"(a[0]), "r"(a[1]), "r"(a[2]), "r"(a[3]), "r"(b0), "r"(b1));
}

// ================= Kernel 1: x[b,f,n,m] -> H[b][m][0..31][n] =================
__global__ __launch_bounds__(256) void k_transpose(const float* __restrict__ x) {
    int id = blockIdx.x;           // ((b*32 + f)*8 + nt)
    int nt = id & 7;
    int f  = (id >> 3) & 31;
    int b  = id >> 8;

    __shared__ float ts[32][65];
    int t  = threadIdx.x;
    int m  = t & 63;
    int nl = t >> 6;               // 0..3
    const float* xp = x + ((size_t)(b * F_IN + f) * CN + nt * 32) * M_;
#pragma unroll
    for (int i = 0; i < 8; ++i) {
        int r = nl + 4 * i;
        ts[r][m] = xp[(size_t)r * M_ + m];
    }
    __syncthreads();
    int nl2 = t & 31;
    int mg  = t >> 5;              // 0..7
#pragma unroll
    for (int i = 0; i < 8; ++i) {
        int mm = mg + 8 * i;
        g_H[((size_t)(b * M_ + mm) * C_CAT + f) * CN + nt * 32 + nl2] = ts[nl2][mm];
    }
}

// ================= Kernel 2: HMMA fused double-hop nconv =================
// One CTA per (base, b, m). D[v(256) x f(32)] = sum_n A[n][v] * x[f][n]
// mma m16n8k16 bf16, fp32 accum, 3-term truncation split.
//
// smem (b32 strides): xs[f=32][np=128] stride 132; As[v=256][16 words] stride 20,
// 2-bit XOR group swizzle -> conflict-free STS and LDSM.
#define AS_STR 20
#define XS_STR 132
#define SM_XS_HI 0u
#define SM_XS_LO 16896u
#define SM_AS_HI 33792u          // 256*20*4 = 20480 B
#define SM_AS_LO 54272u          // + 20480
#define SM_X1    33792u          // fp32 [256][33] (33792 B), aliases As region
#define SM_TOT   74752u

// As word offset, conflict-free swizzle: group' = (j>>2) ^ ((v>>3)&3)
__device__ __forceinline__ uint32_t as_word(int v, int j) {
    return (uint32_t)(v * AS_STR + 4 * (((j >> 2) ^ ((v >> 3) & 3))) + (j & 3));
}

__global__ __launch_bounds__(256, 2) void k_nconv(const float* __restrict__ b0,
                                                  const float* __restrict__ b1,
                                                  const float* __restrict__ b2)
{
    extern __shared__ char smem[];
    uint32_t sb = smem_u32(smem);
    int t   = threadIdx.x;
    int wid = t >> 5;
    int l   = t & 31;

    int id = blockIdx.x;                    // 0..1535
    int kb = id >> 9;
    int bm = id & 511;
    const float* Ag = (kb == 0 ? b0 : (kb == 1 ? b1 : b2)) + (size_t)bm * (CN * CN);
    float* Hbm = g_H + (size_t)bm * (C_CAT * CN);

    // ---- prefetch A chunk 0 (32 n-rows) into registers ----
    float pf[32];
#pragma unroll
    for (int i = 0; i < 32; ++i)
        pf[i] = __ldg(Ag + (size_t)i * CN + t);

    // ---- build xs (hi/lo) from piece 0 [f][n] fp32 ----
    {
        const float2* src = (const float2*)Hbm;
#pragma unroll
        for (int k = 0; k < 16; ++k) {
            int pos = t + 256 * k;          // f = pos>>7, np = pos&127
            int f = pos >> 7, np = pos & 127;
            float2 a = src[pos];
            uint32_t hi2, lo2; split2t(a.x, a.y, hi2, lo2);
            uint32_t off = (uint32_t)(f * XS_STR + np) * 4u;
            *(uint32_t*)(smem + SM_XS_HI + off) = hi2;
            *(uint32_t*)(smem + SM_XS_LO + off) = lo2;
        }
    }

    // ---- per-lane ldmatrix address components ----
    int sub = l >> 3;                       // 0..3
    int s0  = sub & 1;                      // row-half selector
    int s1  = sub >> 1;                     // k-group selector
    int rA  = (32 * wid + 8 * s0 + (l & 7)) * AS_STR;   // A row word-offset (mt=0)
    int arow = (l & 7) + 8 * s0;
    int anpX = 4 * s1;
    uint32_t aX0 = sb + SM_XS_HI + (uint32_t)(arow * XS_STR + anpX) * 4u;
    uint32_t aX1 = sb + SM_XS_HI + (uint32_t)((16 + arow) * XS_STR + anpX) * 4u;
    const uint32_t ALO = SM_AS_LO - SM_AS_HI;   // 20480
    const uint32_t XLO = SM_XS_LO - SM_XS_HI;   // 16896

    int grp = l >> 2, qp = l & 3;

    __syncthreads();

    for (int h = 0; h < 2; ++h) {
        float acc[2][4][4];
#pragma unroll
        for (int mt = 0; mt < 2; ++mt)
#pragma unroll
            for (int nt = 0; nt < 4; ++nt)
#pragma unroll
                for (int e = 0; e < 4; ++e) acc[mt][nt][e] = 0.0f;

        for (int c = 0; c < 8; ++c) {
            // convert prefetched chunk -> As hi/lo (thread owns column v = t)
#pragma unroll
            for (int j = 0; j < 16; ++j) {
                uint32_t hi2, lo2; split2t(pf[2 * j], pf[2 * j + 1], hi2, lo2);
                uint32_t w = as_word(t, j) * 4u;
                *(uint32_t*)(smem + SM_AS_HI + w) = hi2;
                *(uint32_t*)(smem + SM_AS_LO + w) = lo2;
            }
            __syncthreads();

            // prefetch next chunk (overlaps with MMA below)
            if (c < 7) {
                const float* src = Ag + (size_t)(c + 1) * 32 * CN + t;
#pragma unroll
                for (int i = 0; i < 32; ++i) pf[i] = __ldg(src + (size_t)i * CN);
            } else if (h == 0) {
                const float* src = Ag + t;      // hop-2 chunk 0 (L2 hit)
#pragma unroll
                for (int i = 0; i < 32; ++i) pf[i] = __ldg(src + (size_t)i * CN);
            }

            // MMA: 2 k-steps of 16
#pragma unroll
            for (int ks = 0; ks < 2; ++ks) {
                uint32_t npg = 16u * c + 8u * ks;   // x word offset
                uint32_t aH[2][4], aL[2][4], xH[2][4], xL[2][4];
#pragma unroll
                for (int mt = 0; mt < 2; ++mt) {
                    uint32_t swz = (uint32_t)((2 * ks + s1) ^ (2 * mt + s0));
                    uint32_t offA = (uint32_t)(rA + 16 * mt * AS_STR + 4 * (int)swz) * 4u;
                    ldsm4(aH[mt], sb + SM_AS_HI + offA);
                    ldsm4(aL[mt], sb + SM_AS_HI + ALO + offA);
                }
                ldsm4(xH[0], aX0 + npg * 4u);
                ldsm4(xH[1], aX1 + npg * 4u);
                ldsm4(xL[0], aX0 + XLO + npg * 4u);
                ldsm4(xL[1], aX1 + XLO + npg * 4u);
#pragma unroll
                for (int mt = 0; mt < 2; ++mt)
#pragma unroll
                    for (int fb = 0; fb < 2; ++fb) {
                        mma16816(acc[mt][2 * fb],     aH[mt], xH[fb][0], xH[fb][2]);
                        mma16816(acc[mt][2 * fb + 1], aH[mt], xH[fb][1], xH[fb][3]);
                        mma16816(acc[mt][2 * fb],     aL[mt], xH[fb][0], xH[fb][2]);
                        mma16816(acc[mt][2 * fb + 1], aL[mt], xH[fb][1], xH[fb][3]);
                        mma16816(acc[mt][2 * fb],     aH[mt], xL[fb][0], xL[fb][2]);
                        mma16816(acc[mt][2 * fb + 1], aH[mt], xL[fb][1], xL[fb][3]);
                    }
            }
            __syncthreads();
        }

        // ---- epilogue: write piece to global; (h==0) rebuild xs from result ----
        int piece = 1 + 2 * kb + h;
        float* Hp = Hbm + (size_t)(32 * piece) * CN;
#pragma unroll
        for (int mt = 0; mt < 2; ++mt)
#pragma unroll
            for (int nt = 0; nt < 4; ++nt) {
                int v0 = 32 * wid + 16 * mt + grp;
                int f0 = 8 * nt + 2 * qp;
                Hp[(size_t)f0 * CN + v0]           = acc[mt][nt][0];
                Hp[(size_t)(f0 + 1) * CN + v0]     = acc[mt][nt][1];
                Hp[(size_t)f0 * CN + v0 + 8]       = acc[mt][nt][2];
                Hp[(size_t)(f0 + 1) * CN + v0 + 8] = acc[mt][nt][3];
            }

        if (h == 0) {
            float* x1s = (float*)(smem + SM_X1);    // aliases As (idle now)
#pragma unroll
            for (int mt = 0; mt < 2; ++mt)
#pragma unroll
                for (int nt = 0; nt < 4; ++nt) {
                    int v0 = 32 * wid + 16 * mt + grp;
                    int f0 = 8 * nt + 2 * qp;
                    x1s[v0 * 33 + f0]           = acc[mt][nt][0];
                    x1s[v0 * 33 + f0 + 1]       = acc[mt][nt][1];
                    x1s[(v0 + 8) * 33 + f0]     = acc[mt][nt][2];
                    x1s[(v0 + 8) * 33 + f0 + 1] = acc[mt][nt][3];
                }
            __syncthreads();
            // xs[f][n=v] <- x1s[v][f]
            int f = t & 31, g8 = t >> 5;
#pragma unroll
            for (int k = 0; k < 16; ++k) {
                int np = g8 + 8 * k;
                float a0 = x1s[(2 * np) * 33 + f];
                float a1 = x1s[(2 * np + 1) * 33 + f];
                uint32_t hi2, lo2; split2t(a0, a1, hi2, lo2);
                uint32_t off = (uint32_t)(f * XS_STR + np) * 4u;
                *(uint32_t*)(smem + SM_XS_HI + off) = hi2;
                *(uint32_t*)(smem + SM_XS_LO + off) = lo2;
            }
            __syncthreads();
        }
    }
}

// ================= Kernel 3: y[b,o,c,m] = W[o,:] . H[b][m][:][c] + bias[o] =================
__global__ __launch_bounds__(256, 2) void k_final(const float* __restrict__ W,
                                                  const float* __restrict__ bias,
                                                  float* __restrict__ y)
{
    extern __shared__ float smemf[];
    float* Ws = smemf;                      // 224*68 transposed W: Ws[fc][o]
    float* Hs = Ws + C_CAT * WS_STRIDE;     // 2*KC*256

    int bm = blockIdx.x;
    int b  = bm >> 6;
    int m  = bm & 63;
    const float* Hbm = g_H + (size_t)bm * (C_CAT * CN);

    int t  = threadIdx.x;
    int tv = t & 31;
    int og = t >> 5;                        // 0..7

    int lr = t >> 6;
    int lc = (t & 63) * 4;

#pragma unroll
    for (int r = 0; r < 4; ++r)
        cp_async16(smem_u32(&Hs[(lr + 4 * r) * CN + lc]), Hbm + (size_t)(lr + 4 * r) * CN + lc);
    cp_commit();

    for (int i = t; i < C_OUT * C_CAT; i += 256) {
        int o = i / C_CAT, fc = i % C_CAT;
        Ws[fc * WS_STRIDE + o] = W[i];
    }
    float bv[8];
#pragma unroll
    for (int i = 0; i < 8; ++i) bv[i] = bias[8 * og + i];

    uint64_t acc2[4][2][4];
#pragma unroll
    for (int p = 0; p < 4; ++p)
#pragma unroll
        for (int q = 0; q < 2; ++q)
#pragma unroll
            for (int j = 0; j < 4; ++j) acc2[p][q][j] = 0ull;

    const int NCH = C_CAT / KC;  // 14
    for (int ch = 0; ch < NCH; ++ch) {
        float* buf = Hs + (ch & 1) * (KC * CN);
        if (ch < NCH - 1) {
            float* nbuf = Hs + ((ch + 1) & 1) * (KC * CN);
            const float* Hc = Hbm + (size_t)(ch + 1) * KC * CN;
#pragma unroll
            for (int r = 0; r < 4; ++r)
                cp_async16(smem_u32(&nbuf[(lr + 4 * r) * CN + lc]), Hc + (size_t)(lr + 4 * r) * CN + lc);
            cp_commit();
            cp_wait<1>();
        } else {
            cp_wait<0>();
        }
        __syncthreads();
#pragma unroll
        for (int kk = 0; kk < KC; ++kk) {
            float4 w0 = *(const float4*)&Ws[(ch * KC + kk) * WS_STRIDE + 8 * og];
            float4 w1 = *(const float4*)&Ws[(ch * KC + kk) * WS_STRIDE + 8 * og + 4];
            float4 h0 = *(const float4*)&buf[kk * CN + 4 * tv];
            float4 h1 = *(const float4*)&buf[kk * CN + 128 + 4 * tv];
            uint64_t wp[4] = { pk2(w0.x, w0.y), pk2(w0.z, w0.w),
                               pk2(w1.x, w1.y), pk2(w1.z, w1.w) };
            uint64_t hd[2][4] = {
                { pk2(h0.x, h0.x), pk2(h0.y, h0.y), pk2(h0.z, h0.z), pk2(h0.w, h0.w) },
                { pk2(h1.x, h1.x), pk2(h1.y, h1.y), pk2(h1.z, h1.z), pk2(h1.w, h1.w) }
            };
#pragma unroll
            for (int p = 0; p < 4; ++p)
#pragma unroll
                for (int q = 0; q < 2; ++q)
#pragma unroll
                    for (int j = 0; j < 4; ++j)
                        ffma2(acc2[p][q][j], wp[p], hd[q][j]);
        }
        __syncthreads();
    }

#pragma unroll
    for (int p = 0; p < 4; ++p) {
#pragma unroll
        for (int q = 0; q < 2; ++q)
#pragma unroll
            for (int j = 0; j < 4; ++j) {
                float lo, hi;
                upk2(acc2[p][q][j], lo, hi);
                int o0 = 8 * og + 2 * p;
                int c  = 128 * q + 4 * tv + j;
                size_t ob0 = ((size_t)(b * C_OUT + o0) * CN + c) * M_ + m;
                size_t ob1 = ((size_t)(b * C_OUT + o0 + 1) * CN + c) * M_ + m;
                y[ob0] = lo + bv[2 * p];
                y[ob1] = hi + bv[2 * p + 1];
            }
    }
}

// ================= launch =================
extern "C" void kernel_launch(void* const* d_in, const int* in_sizes, int n_in,
                              void* d_out, int out_size) {
    const float* x    = (const float*)d_in[0];
    const float* b0   = (const float*)d_in[1];
    const float* b1   = (const float*)d_in[2];
    const float* b2   = (const float*)d_in[3];
    const float* W    = (const float*)d_in[4];
    const float* bias = (const float*)d_in[5];
    float* y = (float*)d_out;

    const int SMEM_K3 = (C_CAT * WS_STRIDE + 2 * KC * CN) * 4;     // 93,696 B
    cudaFuncSetAttribute(k_nconv, cudaFuncAttributeMaxDynamicSharedMemorySize, (int)SM_TOT);
    cudaFuncSetAttribute(k_final, cudaFuncAttributeMaxDynamicSharedMemorySize, SMEM_K3);

    k_transpose<<<2048, 256>>>(x);
    k_nconv<<<1536, 256, SM_TOT>>>(b0, b1, b2);
    k_final<<<512, 256, SMEM_K3>>>(W, bias, y);
}

// round 10
// speedup vs baseline: 1.2369x; 1.0001x over previous
#include <cuda_runtime.h>
#include <cstdint>

#define B_    8
#define F_IN  32
#define CN    256
#define M_    64
#define C_OUT 64
#define C_CAT 224   // (2*3+1)*32

// Scratch: H[b][m][fc][c], fc in [0,224): piece p at fc=32p.
// All pieces stored pre-rounded to tf32 (fp32 bits with low mantissa zeroed).
__device__ float g_H[(size_t)B_ * M_ * C_CAT * CN];

// ================= helpers =================
__device__ __forceinline__ uint32_t smem_u32(const void* p) {
    uint32_t a;
    asm("{ .reg .u64 t; cvta.to.shared.u64 t, %1; cvt.u32.u64 %0, t; }" : "=r"(a) : "l"(p));
    return a;
}
__device__ __forceinline__ void cp_async16(uint32_t sa, const void* g) {
    asm volatile("cp.async.cg.shared.global [%0], [%1], 16;\n" :: "r"(sa), "l"(g));
}
__device__ __forceinline__ void cp_commit() { asm volatile("cp.async.commit_group;\n"); }
template<int N> __device__ __forceinline__ void cp_wait() {
    asm volatile("cp.async.wait_group %0;\n" :: "n"(N));
}
__device__ __forceinline__ uint32_t f2tf32(float f) {
    uint32_t u; asm("cvt.rna.tf32.f32 %0, %1;" : "=r"(u) : "f"(f)); return u;
}
__device__ __forceinline__ uint32_t lds32(uint32_t a) {
    uint32_t v; asm("ld.shared.b32 %0, [%1];" : "=r"(v) : "r"(a)); return v;
}
__device__ __forceinline__ void sts32(uint32_t a, uint32_t v) {
    asm volatile("st.shared.b32 [%0], %1;" :: "r"(a), "r"(v));
}
// mma m16n8k8 row.col tf32 -> f32
__device__ __forceinline__ void mma_tf32(float c[4], const uint32_t a[4],
                                         uint32_t b0, uint32_t b1) {
    asm volatile("mma.sync.aligned.m16n8k8.row.col.f32.tf32.tf32.f32 "
                 "{%0,%1,%2,%3},{%4,%5,%6,%7},{%8,%9},{%0,%1,%2,%3};"
                 : "+f"(c[0]), "+f"(c[1]), "+f"(c[2]), "+f"(c[3])
                 : "r"(a[0]), "r"(a[1]), "r"(a[2]), "r"(a[3]), "r"(b0), "r"(b1));
}

// ================= Kernel 1: x[b,f,n,m] -> H piece0 [b][m][f][n], tf32-rounded =================
__global__ __launch_bounds__(256) void k_transpose(const float* __restrict__ x) {
    int id = blockIdx.x;           // ((b*32 + f)*8 + nt)
    int nt = id & 7;
    int f  = (id >> 3) & 31;
    int b  = id >> 8;

    __shared__ float ts[32][65];
    int t  = threadIdx.x;
    int m  = t & 63;
    int nl = t >> 6;               // 0..3
    const float* xp = x + ((size_t)(b * F_IN + f) * CN + nt * 32) * M_;
#pragma unroll
    for (int i = 0; i < 8; ++i) {
        int r = nl + 4 * i;
        ts[r][m] = xp[(size_t)r * M_ + m];
    }
    __syncthreads();
    int nl2 = t & 31;
    int mg  = t >> 5;              // 0..7
#pragma unroll
    for (int i = 0; i < 8; ++i) {
        int mm = mg + 8 * i;
        g_H[((size_t)(b * M_ + mm) * C_CAT + f) * CN + nt * 32 + nl2] =
            __uint_as_float(f2tf32(ts[nl2][mm]));
    }
}

// ================= Kernel 2: tf32 MMA fused double-hop nconv =================
// One CTA per (base, b, m). D[v(256) x f(32)] = sum_n A[n][v] * x[f][n]
// mma m16n8k8 tf32, fp32 accum. Double-buffered As, ONE sync per chunk.
//
// smem (words): xs[f=32][n: stride 260]; As 2 x [n=32][v: stride 264];
// x1s fp32 [256][33] aliases As buffer 1.
#define SM_XS  0u
#define SM_AS  33280u
#define AS_BUF 33792u
#define SM_X1  (SM_AS + AS_BUF)
#define SM_TOT (SM_AS + 2u * AS_BUF)   // 100,864 B -> occupancy 2

__global__ __launch_bounds__(256, 2) void k_nconv(const float* __restrict__ b0,
                                                  const float* __restrict__ b1,
                                                  const float* __restrict__ b2)
{
    extern __shared__ char smem[];
    uint32_t sb = smem_u32(smem);
    int t   = threadIdx.x;
    int wid = t >> 5;
    int l   = t & 31;
    int r   = l >> 2;               // groupID
    int cq  = l & 3;                // threadID_in_group

    int id = blockIdx.x;            // 0..1535
    int kb = id >> 9;
    int bm = id & 511;
    const float* Ag = (kb == 0 ? b0 : (kb == 1 ? b1 : b2)) + (size_t)bm * (CN * CN);
    float* Hbm = g_H + (size_t)bm * (C_CAT * CN);

    // ---- prologue: LDG chunk 0 ----
    float pf[32];
#pragma unroll
    for (int i = 0; i < 32; ++i)
        pf[i] = __ldg(Ag + (size_t)i * CN + t);

    // xs copy from piece0 (already tf32 bits — no cvt)
    {
        uint32_t* xsw = (uint32_t*)(smem + SM_XS);
        const uint32_t* src = (const uint32_t*)Hbm;
#pragma unroll
        for (int k = 0; k < 32; ++k) {
            int idx = t + 256 * k;
            int f = idx >> 8, n = idx & 255;
            xsw[f * 260 + n] = src[idx];
        }
    }

    // convert chunk 0 -> As buf0 (thread owns column v = t; bank = 8i + t, conflict-free)
    {
        uint32_t dst = sb + SM_AS + (uint32_t)t * 4u;
#pragma unroll
        for (int i = 0; i < 32; ++i)
            sts32(dst + (uint32_t)i * 1056u, f2tf32(pf[i]));
    }
    // LDG chunk 1
#pragma unroll
    for (int i = 0; i < 32; ++i)
        pf[i] = __ldg(Ag + (size_t)(32 + i) * CN + t);

    __syncthreads();

    // per-lane fragment base addresses
    // A: a0 = As[n=8ks+cq][v=32wid+16mt+r]; word = (8ks+cq)*264 + v
    uint32_t baseA0 = sb + SM_AS + (uint32_t)(cq * 264 + 32 * wid + r) * 4u;   // +64B per mt
    // B: b0 = xs[f=8nt+r][n=8ks+cq]; word = f*260 + n
    uint32_t baseB0 = sb + SM_XS + (uint32_t)(r * 260 + cq) * 4u;              // +8320B per nt

    float acc[2][4][4];
#pragma unroll
    for (int mt = 0; mt < 2; ++mt)
#pragma unroll
        for (int nt = 0; nt < 4; ++nt)
#pragma unroll
            for (int e = 0; e < 4; ++e) acc[mt][nt][e] = 0.0f;

    for (int ci = 0; ci < 16; ++ci) {
        // ---- MMA(ci) on As[ci&1] ----
        uint32_t abuf = (uint32_t)(ci & 1) * AS_BUF;
        uint32_t bofs = (uint32_t)(32 * (ci & 7)) * 4u;   // chunk n-offset in xs
#pragma unroll
        for (int ks = 0; ks < 4; ++ks) {
            uint32_t a[2][4], bb[4][2];
#pragma unroll
            for (int mt = 0; mt < 2; ++mt) {
                uint32_t ab = baseA0 + abuf + (uint32_t)mt * 64u + (uint32_t)ks * 8448u;
                a[mt][0] = lds32(ab);           // (n0+cq,    v0+r)
                a[mt][1] = lds32(ab + 32u);     // (n0+cq,    v0+r+8)
                a[mt][2] = lds32(ab + 4224u);   // (n0+cq+4,  v0+r)
                a[mt][3] = lds32(ab + 4256u);   // (n0+cq+4,  v0+r+8)
            }
#pragma unroll
            for (int nt = 0; nt < 4; ++nt) {
                uint32_t bx = baseB0 + (uint32_t)nt * 8320u + bofs + (uint32_t)ks * 32u;
                bb[nt][0] = lds32(bx);
                bb[nt][1] = lds32(bx + 16u);
            }
#pragma unroll
            for (int mt = 0; mt < 2; ++mt)
#pragma unroll
                for (int nt = 0; nt < 4; ++nt)
                    mma_tf32(acc[mt][nt], a[mt], bb[nt][0], bb[nt][1]);
        }

        // ---- convert(ci+1) -> As[(ci+1)&1] (safe: last read by MMA(ci-1), pre-sync) ----
        if (ci < 15) {
            uint32_t dst = sb + SM_AS + (uint32_t)((ci + 1) & 1) * AS_BUF + (uint32_t)t * 4u;
#pragma unroll
            for (int i = 0; i < 32; ++i)
                sts32(dst + (uint32_t)i * 1056u, f2tf32(pf[i]));
        }
        // ---- LDG chunk (ci+2)&7 (hop-2 chunks re-hit L2) ----
        if (ci < 14) {
            const float* src = Ag + (size_t)(((ci + 2) & 7) * 32) * CN + t;
#pragma unroll
            for (int i = 0; i < 32; ++i)
                pf[i] = __ldg(src + (size_t)i * CN);
        }
        __syncthreads();

        // ---- hop boundary ----
        if (ci == 7) {
            float* Hp  = Hbm + (size_t)(32 * (1 + 2 * kb)) * CN;
            float* x1s = (float*)(smem + SM_X1);   // aliases As buf1 (free: MMA(7) done)
#pragma unroll
            for (int mt = 0; mt < 2; ++mt)
#pragma unroll
                for (int nt = 0; nt < 4; ++nt) {
                    int v0 = 32 * wid + 16 * mt + r;
                    int f0 = 8 * nt + 2 * cq;
                    float a0 = acc[mt][nt][0], a1 = acc[mt][nt][1];
                    float a2 = acc[mt][nt][2], a3 = acc[mt][nt][3];
                    Hp[(size_t)f0 * CN + v0]           = __uint_as_float(f2tf32(a0));
                    Hp[(size_t)(f0 + 1) * CN + v0]     = __uint_as_float(f2tf32(a1));
                    Hp[(size_t)f0 * CN + v0 + 8]       = __uint_as_float(f2tf32(a2));
                    Hp[(size_t)(f0 + 1) * CN + v0 + 8] = __uint_as_float(f2tf32(a3));
                    x1s[v0 * 33 + f0]           = a0;
                    x1s[v0 * 33 + f0 + 1]       = a1;
                    x1s[(v0 + 8) * 33 + f0]     = a2;
                    x1s[(v0 + 8) * 33 + f0 + 1] = a3;
                    acc[mt][nt][0] = acc[mt][nt][1] = acc[mt][nt][2] = acc[mt][nt][3] = 0.0f;
                }
            __syncthreads();
            // rebuild xs[f][n] <- tf32(x1s[n][f])
            {
                uint32_t* xsw = (uint32_t*)(smem + SM_XS);
                const float* x1r = (const float*)(smem + SM_X1);
                int f = l;
#pragma unroll
                for (int k = 0; k < 32; ++k) {
                    int n = wid + 8 * k;
                    xsw[f * 260 + n] = f2tf32(x1r[n * 33 + f]);
                }
            }
            __syncthreads();
        }
    }

    // ---- hop2 epilogue ----
    {
        float* Hp = Hbm + (size_t)(32 * (2 + 2 * kb)) * CN;
#pragma unroll
        for (int mt = 0; mt < 2; ++mt)
#pragma unroll
            for (int nt = 0; nt < 4; ++nt) {
                int v0 = 32 * wid + 16 * mt + r;
                int f0 = 8 * nt + 2 * cq;
                Hp[(size_t)f0 * CN + v0]           = __uint_as_float(f2tf32(acc[mt][nt][0]));
                Hp[(size_t)(f0 + 1) * CN + v0]     = __uint_as_float(f2tf32(acc[mt][nt][1]));
                Hp[(size_t)f0 * CN + v0 + 8]       = __uint_as_float(f2tf32(acc[mt][nt][2]));
                Hp[(size_t)(f0 + 1) * CN + v0 + 8] = __uint_as_float(f2tf32(acc[mt][nt][3]));
            }
    }
}

// ================= Kernel 3: tf32 MMA channel-mix =================
// One CTA per (b,m): y[o=64][c=256] = W[o][fc=224] * H[fc][c] + bias[o]
// Warp w owns c-range 32 (4 n-tiles of 8); o = 4 m-tiles of 16. H is tf32-clean.
#define KF_WS   0u          // Ws[o=64][fc: stride 228] tf32 -> 58368 B
#define KF_HS   58368u      // 2 x [fc=16][c: stride 264] fp32(tf32 bits) -> 2*16896
#define KF_HBUF 16896u
#define KF_TOT  (58368u + 2u * 16896u)   // 92,160 B -> occupancy 2

__global__ __launch_bounds__(256, 2) void k_final(const float* __restrict__ W,
                                                  const float* __restrict__ bias,
                                                  float* __restrict__ y)
{
    extern __shared__ char smem[];
    uint32_t sb = smem_u32(smem);
    int t  = threadIdx.x;
    int w  = t >> 5;
    int l  = t & 31;
    int r  = l >> 2;
    int cq = l & 3;

    int bm = blockIdx.x;
    int b  = bm >> 6;
    int m  = bm & 63;
    const float* Hbm = g_H + (size_t)bm * (C_CAT * CN);

    int srow = t >> 6;          // 0..3
    int scol = (t & 63) * 4;    // word col

    // prologue: cp.async H chunk 0 (16 fc-rows) -> Hs buf0
#pragma unroll
    for (int k = 0; k < 4; ++k) {
        int row = srow + 4 * k;
        cp_async16(sb + KF_HS + (uint32_t)(row * 264 + scol) * 4u, Hbm + row * CN + scol);
    }
    cp_commit();

    // build Ws (tf32)
    {
        uint32_t* wsw = (uint32_t*)(smem + KF_WS);
        for (int i = t; i < C_OUT * C_CAT; i += 256) {
            int o = i / C_CAT, fc = i % C_CAT;
            wsw[o * 228 + fc] = f2tf32(W[i]);
        }
    }
    float bv[4][2];
#pragma unroll
    for (int mt = 0; mt < 4; ++mt) {
        bv[mt][0] = bias[16 * mt + r];
        bv[mt][1] = bias[16 * mt + r + 8];
    }

    float acc[4][4][4];
#pragma unroll
    for (int mt = 0; mt < 4; ++mt)
#pragma unroll
        for (int nt = 0; nt < 4; ++nt)
#pragma unroll
            for (int e = 0; e < 4; ++e) acc[mt][nt][e] = 0.0f;

    // a0 = Ws[o=16mt+r][k+cq]: word = (16mt+r)*228 + k + cq
    uint32_t baseA0 = sb + KF_WS + (uint32_t)(r * 228 + cq) * 4u;          // +14592B per mt
    // b0 = Hs[fc=8kk+cq][c=32w+8nt+r]: word = (8kk+cq)*264 + c
    uint32_t baseB0 = sb + KF_HS + (uint32_t)(cq * 264 + 32 * w + r) * 4u; // +32B per nt

    for (int ch = 0; ch < 14; ++ch) {
        if (ch < 13) {
            uint32_t dst = sb + KF_HS + (uint32_t)((ch + 1) & 1) * KF_HBUF;
            const float* src = Hbm + (size_t)(16 * (ch + 1)) * CN;
#pragma unroll
            for (int k = 0; k < 4; ++k) {
                int row = srow + 4 * k;
                cp_async16(dst + (uint32_t)(row * 264 + scol) * 4u, src + row * CN + scol);
            }
            cp_commit();
            cp_wait<1>();
        } else {
            cp_wait<0>();
        }
        __syncthreads();

        uint32_t hb = (uint32_t)(ch & 1) * KF_HBUF;
#pragma unroll
        for (int kk = 0; kk < 2; ++kk) {
            uint32_t kofs = (uint32_t)(16 * ch + 8 * kk) * 4u;
            uint32_t a[4][4], bb[4][2];
#pragma unroll
            for (int mt = 0; mt < 4; ++mt) {
                uint32_t ab = baseA0 + (uint32_t)mt * 14592u + kofs;
                a[mt][0] = lds32(ab);            // (o0+r,   k+cq)
                a[mt][1] = lds32(ab + 7296u);    // (o0+r+8, k+cq)
                a[mt][2] = lds32(ab + 16u);      // (o0+r,   k+cq+4)
                a[mt][3] = lds32(ab + 7312u);    // (o0+r+8, k+cq+4)
            }
#pragma unroll
            for (int nt = 0; nt < 4; ++nt) {
                uint32_t bx = baseB0 + hb + (uint32_t)nt * 32u + (uint32_t)kk * 8448u;
                bb[nt][0] = lds32(bx);
                bb[nt][1] = lds32(bx + 4224u);   // fc + 4
            }
#pragma unroll
            for (int mt = 0; mt < 4; ++mt)
#pragma unroll
                for (int nt = 0; nt < 4; ++nt)
                    mma_tf32(acc[mt][nt], a[mt], bb[nt][0], bb[nt][1]);
        }
        __syncthreads();
    }

    // epilogue: y[((b*64+o)*256+c)*64 + m]
#pragma unroll
    for (int mt = 0; mt < 4; ++mt)
#pragma unroll
        for (int nt = 0; nt < 4; ++nt) {
            int o0 = 16 * mt + r;
            int c0 = 32 * w + 8 * nt + 2 * cq;
            y[((size_t)(b * C_OUT + o0) * CN + c0) * M_ + m]         = acc[mt][nt][0] + bv[mt][0];
            y[((size_t)(b * C_OUT + o0) * CN + c0 + 1) * M_ + m]     = acc[mt][nt][1] + bv[mt][0];
            y[((size_t)(b * C_OUT + o0 + 8) * CN + c0) * M_ + m]     = acc[mt][nt][2] + bv[mt][1];
            y[((size_t)(b * C_OUT + o0 + 8) * CN + c0 + 1) * M_ + m] = acc[mt][nt][3] + bv[mt][1];
        }
}

// ================= launch =================
extern "C" void kernel_launch(void* const* d_in, const int* in_sizes, int n_in,
                              void* d_out, int out_size) {
    const float* x    = (const float*)d_in[0];
    const float* b0   = (const float*)d_in[1];
    const float* b1   = (const float*)d_in[2];
    const float* b2   = (const float*)d_in[3];
    const float* W    = (const float*)d_in[4];
    const float* bias = (const float*)d_in[5];
    float* y = (float*)d_out;

    cudaFuncSetAttribute(k_nconv, cudaFuncAttributeMaxDynamicSharedMemorySize, (int)SM_TOT);
    cudaFuncSetAttribute(k_final, cudaFuncAttributeMaxDynamicSharedMemorySize, (int)KF_TOT);

    k_transpose<<<2048, 256>>>(x);
    k_nconv<<<1536, 256, SM_TOT>>>(b0, b1, b2);
    k_final<<<512, 256, KF_TOT>>>(W, bias, y);
}

// round 12
// speedup vs baseline: 1.2890x; 1.0421x over previous
#include <cuda_runtime.h>
#include <cstdint>

#define B_    8
#define F_IN  32
#define CN    256
#define M_    64
#define C_OUT 64
#define C_CAT 224   // (2*3+1)*32

// Scratch: H[b][m][fc][c], fc in [0,224): piece p at fc=32p.
// All pieces stored pre-rounded to tf32 (fp32 bits with low mantissa zeroed).
__device__ float g_H[(size_t)B_ * M_ * C_CAT * CN];

// ================= helpers =================
__device__ __forceinline__ uint32_t smem_u32(const void* p) {
    uint32_t a;
    asm("{ .reg .u64 t; cvta.to.shared.u64 t, %1; cvt.u32.u64 %0, t; }" : "=r"(a) : "l"(p));
    return a;
}
__device__ __forceinline__ void cp_async16(uint32_t sa, const void* g) {
    asm volatile("cp.async.cg.shared.global [%0], [%1], 16;\n" :: "r"(sa), "l"(g));
}
__device__ __forceinline__ void cp_commit() { asm volatile("cp.async.commit_group;\n"); }
template<int N> __device__ __forceinline__ void cp_wait() {
    asm volatile("cp.async.wait_group %0;\n" :: "n"(N));
}
__device__ __forceinline__ uint32_t f2tf32(float f) {
    uint32_t u; asm("cvt.rna.tf32.f32 %0, %1;" : "=r"(u) : "f"(f)); return u;
}
__device__ __forceinline__ uint32_t lds32(uint32_t a) {
    uint32_t v; asm("ld.shared.b32 %0, [%1];" : "=r"(v) : "r"(a)); return v;
}
__device__ __forceinline__ void sts128(uint32_t a, uint32_t x, uint32_t y,
                                       uint32_t z, uint32_t w) {
    asm volatile("st.shared.v4.b32 [%0], {%1,%2,%3,%4};"
                 :: "r"(a), "r"(x), "r"(y), "r"(z), "r"(w));
}
// eviction policy: keep A slabs resident in L2 for the hop-2 re-read
__device__ __forceinline__ uint64_t mk_policy_evict_last() {
    uint64_t pol;
    asm("createpolicy.fractional.L2::evict_last.b64 %0, 1.0;" : "=l"(pol));
    return pol;
}
// A-stream load: 16B vectorized with L2 cache-hint policy
__device__ __forceinline__ float4 ldg128_pol(const float4* p, uint64_t pol) {
    float4 v;
    asm volatile("ld.global.L2::cache_hint.v4.f32 {%0,%1,%2,%3}, [%4], %5;"
                 : "=f"(v.x), "=f"(v.y), "=f"(v.z), "=f"(v.w) : "l"(p), "l"(pol));
    return v;
}
// mma m16n8k8 row.col tf32 -> f32
__device__ __forceinline__ void mma_tf32(float c[4], const uint32_t a[4],
                                         uint32_t b0, uint32_t b1) {
    asm volatile("mma.sync.aligned.m16n8k8.row.col.f32.tf32.tf32.f32 "
                 "{%0,%1,%2,%3},{%4,%5,%6,%7},{%8,%9},{%0,%1,%2,%3};"
                 : "+f"(c[0]), "+f"(c[1]), "+f"(c[2]), "+f"(c[3])
                 : "r"(a[0]), "r"(a[1]), "r"(a[2]), "r"(a[3]), "r"(b0), "r"(b1));
}

// ================= Kernel 1: x[b,f,n,m] -> H piece0 [b][m][f][n], tf32-rounded =================
__global__ __launch_bounds__(256) void k_transpose(const float* __restrict__ x) {
    int id = blockIdx.x;           // ((b*32 + f)*8 + nt)
    int nt = id & 7;
    int f  = (id >> 3) & 31;
    int b  = id >> 8;

    __shared__ float ts[32][65];
    int t  = threadIdx.x;
    int m  = t & 63;
    int nl = t >> 6;               // 0..3
    const float* xp = x + ((size_t)(b * F_IN + f) * CN + nt * 32) * M_;
#pragma unroll
    for (int i = 0; i < 8; ++i) {
        int r = nl + 4 * i;
        ts[r][m] = xp[(size_t)r * M_ + m];
    }
    __syncthreads();
    int nl2 = t & 31;
    int mg  = t >> 5;              // 0..7
#pragma unroll
    for (int i = 0; i < 8; ++i) {
        int mm = mg + 8 * i;
        __stcs(&g_H[((size_t)(b * M_ + mm) * C_CAT + f) * CN + nt * 32 + nl2],
               __uint_as_float(f2tf32(ts[nl2][mm])));
    }
}

// ================= Kernel 2: tf32 MMA fused double-hop nconv =================
// One CTA per (base, b, m). D[v(256) x f(32)] = sum_n A[n][v] * x[f][n]
// mma m16n8k8 tf32, fp32 accum. Double-buffered As, ONE sync per chunk.
// A streamed via LDG.128 + evict_last policy; piece stores via st.cs.
//
// smem (words): xs[f=32][n: stride 260]; As 2 x [n=32][v: stride 264];
// x1s fp32 [256][33] aliases As buffer 1.
#define SM_XS  0u
#define SM_AS  33280u
#define AS_BUF 33792u
#define SM_X1  (SM_AS + AS_BUF)
#define SM_TOT (SM_AS + 2u * AS_BUF)   // 100,864 B -> occupancy 2

__global__ __launch_bounds__(256, 2) void k_nconv(const float* __restrict__ b0,
                                                  const float* __restrict__ b1,
                                                  const float* __restrict__ b2)
{
    extern __shared__ char smem[];
    uint32_t sb = smem_u32(smem);
    int t   = threadIdx.x;
    int wid = t >> 5;
    int l   = t & 31;
    int r   = l >> 2;               // groupID
    int cq  = l & 3;                // threadID_in_group

    int id = blockIdx.x;            // 0..1535
    int kb = id >> 9;
    int bm = id & 511;
    const float* Ag = (kb == 0 ? b0 : (kb == 1 ? b1 : b2)) + (size_t)bm * (CN * CN);
    const float4* Ag4 = (const float4*)Ag;
    float* Hbm = g_H + (size_t)bm * (C_CAT * CN);

    uint64_t pol = mk_policy_evict_last();

    int rowg = t >> 6;              // 0..3  (A-load row group)
    int c4   = t & 63;              // float4 column

    // ---- prologue: LDG.128 chunk 0 ----
    float4 pf4[8];
#pragma unroll
    for (int k = 0; k < 8; ++k)
        pf4[k] = ldg128_pol(Ag4 + (size_t)((rowg + 4 * k) * 64 + c4), pol);

    // xs copy from piece0 (already tf32 bits — no cvt)
    {
        uint32_t* xsw = (uint32_t*)(smem + SM_XS);
        const uint32_t* src = (const uint32_t*)Hbm;
#pragma unroll
        for (int k = 0; k < 32; ++k) {
            int idx = t + 256 * k;
            int f = idx >> 8, n = idx & 255;
            xsw[f * 260 + n] = src[idx];
        }
    }

    // convert chunk 0 -> As buf0 (STS.128, conflict-free)
    {
        uint32_t dst = sb + SM_AS + (uint32_t)(rowg * 264 + 4 * c4) * 4u;
#pragma unroll
        for (int k = 0; k < 8; ++k)
            sts128(dst + (uint32_t)k * 4224u,
                   f2tf32(pf4[k].x), f2tf32(pf4[k].y), f2tf32(pf4[k].z), f2tf32(pf4[k].w));
    }
    // LDG chunk 1
#pragma unroll
    for (int k = 0; k < 8; ++k)
        pf4[k] = ldg128_pol(Ag4 + (size_t)((32 + rowg + 4 * k) * 64 + c4), pol);

    __syncthreads();

    // per-lane fragment base addresses
    // A: a0 = As[n=8ks+cq][v=32wid+16mt+r]; word = (8ks+cq)*264 + v
    uint32_t baseA0 = sb + SM_AS + (uint32_t)(cq * 264 + 32 * wid + r) * 4u;   // +64B per mt
    // B: b0 = xs[f=8nt+r][n=8ks+cq]; word = f*260 + n
    uint32_t baseB0 = sb + SM_XS + (uint32_t)(r * 260 + cq) * 4u;              // +8320B per nt

    float acc[2][4][4];
#pragma unroll
    for (int mt = 0; mt < 2; ++mt)
#pragma unroll
        for (int nt = 0; nt < 4; ++nt)
#pragma unroll
            for (int e = 0; e < 4; ++e) acc[mt][nt][e] = 0.0f;

    for (int ci = 0; ci < 16; ++ci) {
        // ---- MMA(ci) on As[ci&1] ----
        uint32_t abuf = (uint32_t)(ci & 1) * AS_BUF;
        uint32_t bofs = (uint32_t)(32 * (ci & 7)) * 4u;   // chunk n-offset in xs
#pragma unroll
        for (int ks = 0; ks < 4; ++ks) {
            uint32_t a[2][4], bb[4][2];
#pragma unroll
            for (int mt = 0; mt < 2; ++mt) {
                uint32_t ab = baseA0 + abuf + (uint32_t)mt * 64u + (uint32_t)ks * 8448u;
                a[mt][0] = lds32(ab);           // (n0+cq,    v0+r)
                a[mt][1] = lds32(ab + 32u);     // (n0+cq,    v0+r+8)
                a[mt][2] = lds32(ab + 4224u);   // (n0+cq+4,  v0+r)
                a[mt][3] = lds32(ab + 4256u);   // (n0+cq+4,  v0+r+8)
            }
#pragma unroll
            for (int nt = 0; nt < 4; ++nt) {
                uint32_t bx = baseB0 + (uint32_t)nt * 8320u + bofs + (uint32_t)ks * 32u;
                bb[nt][0] = lds32(bx);
                bb[nt][1] = lds32(bx + 16u);
            }
#pragma unroll
            for (int mt = 0; mt < 2; ++mt)
#pragma unroll
                for (int nt = 0; nt < 4; ++nt)
                    mma_tf32(acc[mt][nt], a[mt], bb[nt][0], bb[nt][1]);
        }

        // ---- convert(ci+1) -> As[(ci+1)&1] (safe: last read by MMA(ci-1), pre-sync) ----
        if (ci < 15) {
            uint32_t dst = sb + SM_AS + (uint32_t)((ci + 1) & 1) * AS_BUF
                         + (uint32_t)(rowg * 264 + 4 * c4) * 4u;
#pragma unroll
            for (int k = 0; k < 8; ++k)
                sts128(dst + (uint32_t)k * 4224u,
                       f2tf32(pf4[k].x), f2tf32(pf4[k].y), f2tf32(pf4[k].z), f2tf32(pf4[k].w));
        }
        // ---- LDG chunk (ci+2)&7 (hop-2 chunks should hit L2 via evict_last) ----
        if (ci < 14) {
            const float4* src = Ag4 + (size_t)(((ci + 2) & 7) * 32) * 64;
#pragma unroll
            for (int k = 0; k < 8; ++k)
                pf4[k] = ldg128_pol(src + (size_t)((rowg + 4 * k) * 64 + c4), pol);
        }
        __syncthreads();

        // ---- hop boundary ----
        if (ci == 7) {
            float* Hp  = Hbm + (size_t)(32 * (1 + 2 * kb)) * CN;
            float* x1s = (float*)(smem + SM_X1);   // aliases As buf1 (free: MMA(7) done)
#pragma unroll
            for (int mt = 0; mt < 2; ++mt)
#pragma unroll
                for (int nt = 0; nt < 4; ++nt) {
                    int v0 = 32 * wid + 16 * mt + r;
                    int f0 = 8 * nt + 2 * cq;
                    float a0 = acc[mt][nt][0], a1 = acc[mt][nt][1];
                    float a2 = acc[mt][nt][2], a3 = acc[mt][nt][3];
                    __stcs(&Hp[(size_t)f0 * CN + v0],           __uint_as_float(f2tf32(a0)));
                    __stcs(&Hp[(size_t)(f0 + 1) * CN + v0],     __uint_as_float(f2tf32(a1)));
                    __stcs(&Hp[(size_t)f0 * CN + v0 + 8],       __uint_as_float(f2tf32(a2)));
                    __stcs(&Hp[(size_t)(f0 + 1) * CN + v0 + 8], __uint_as_float(f2tf32(a3)));
                    x1s[v0 * 33 + f0]           = a0;
                    x1s[v0 * 33 + f0 + 1]       = a1;
                    x1s[(v0 + 8) * 33 + f0]     = a2;
                    x1s[(v0 + 8) * 33 + f0 + 1] = a3;
                    acc[mt][nt][0] = acc[mt][nt][1] = acc[mt][nt][2] = acc[mt][nt][3] = 0.0f;
                }
            __syncthreads();
            // rebuild xs[f][n] <- tf32(x1s[n][f])
            {
                uint32_t* xsw = (uint32_t*)(smem + SM_XS);
                const float* x1r = (const float*)(smem + SM_X1);
                int f = l;
#pragma unroll
                for (int k = 0; k < 32; ++k) {
                    int n = wid + 8 * k;
                    xsw[f * 260 + n] = f2tf32(x1r[n * 33 + f]);
                }
            }
            __syncthreads();
        }
    }

    // ---- hop2 epilogue ----
    {
        float* Hp = Hbm + (size_t)(32 * (2 + 2 * kb)) * CN;
#pragma unroll
        for (int mt = 0; mt < 2; ++mt)
#pragma unroll
            for (int nt = 0; nt < 4; ++nt) {
                int v0 = 32 * wid + 16 * mt + r;
                int f0 = 8 * nt + 2 * cq;
                __stcs(&Hp[(size_t)f0 * CN + v0],           __uint_as_float(f2tf32(acc[mt][nt][0])));
                __stcs(&Hp[(size_t)(f0 + 1) * CN + v0],     __uint_as_float(f2tf32(acc[mt][nt][1])));
                __stcs(&Hp[(size_t)f0 * CN + v0 + 8],       __uint_as_float(f2tf32(acc[mt][nt][2])));
                __stcs(&Hp[(size_t)(f0 + 1) * CN + v0 + 8], __uint_as_float(f2tf32(acc[mt][nt][3])));
            }
    }
}

// ================= Kernel 3: tf32 MMA channel-mix =================
// One CTA per (b,m): y[o=64][c=256] = W[o][fc=224] * H[fc][c] + bias[o]
#define KF_WS   0u          // Ws[o=64][fc: stride 228] tf32 -> 58368 B
#define KF_HS   58368u      // 2 x [fc=16][c: stride 264] fp32(tf32 bits) -> 2*16896
#define KF_HBUF 16896u
#define KF_TOT  (58368u + 2u * 16896u)   // 92,160 B -> occupancy 2

__global__ __launch_bounds__(256, 2) void k_final(const float* __restrict__ W,
                                                  const float* __restrict__ bias,
                                                  float* __restrict__ y)
{
    extern __shared__ char smem[];
    uint32_t sb = smem_u32(smem);
    int t  = threadIdx.x;
    int w  = t >> 5;
    int l  = t & 31;
    int r  = l >> 2;
    int cq = l & 3;

    int bm = blockIdx.x;
    int b  = bm >> 6;
    int m  = bm & 63;
    const float* Hbm = g_H + (size_t)bm * (C_CAT * CN);

    int srow = t >> 6;          // 0..3
    int scol = (t & 63) * 4;    // word col

    // prologue: cp.async H chunk 0 (16 fc-rows) -> Hs buf0
#pragma unroll
    for (int k = 0; k < 4; ++k) {
        int row = srow + 4 * k;
        cp_async16(sb + KF_HS + (uint32_t)(row * 264 + scol) * 4u, Hbm + row * CN + scol);
    }
    cp_commit();

    // build Ws (tf32)
    {
        uint32_t* wsw = (uint32_t*)(smem + KF_WS);
        for (int i = t; i < C_OUT * C_CAT; i += 256) {
            int o = i / C_CAT, fc = i % C_CAT;
            wsw[o * 228 + fc] = f2tf32(W[i]);
        }
    }
    float bv[4][2];
#pragma unroll
    for (int mt = 0; mt < 4; ++mt) {
        bv[mt][0] = bias[16 * mt + r];
        bv[mt][1] = bias[16 * mt + r + 8];
    }

    float acc[4][4][4];
#pragma unroll
    for (int mt = 0; mt < 4; ++mt)
#pragma unroll
        for (int nt = 0; nt < 4; ++nt)
#pragma unroll
            for (int e = 0; e < 4; ++e) acc[mt][nt][e] = 0.0f;

    uint32_t baseA0 = sb + KF_WS + (uint32_t)(r * 228 + cq) * 4u;          // +14592B per mt
    uint32_t baseB0 = sb + KF_HS + (uint32_t)(cq * 264 + 32 * w + r) * 4u; // +32B per nt

    for (int ch = 0; ch < 14; ++ch) {
        if (ch < 13) {
            uint32_t dst = sb + KF_HS + (uint32_t)((ch + 1) & 1) * KF_HBUF;
            const float* src = Hbm + (size_t)(16 * (ch + 1)) * CN;
#pragma unroll
            for (int k = 0; k < 4; ++k) {
                int row = srow + 4 * k;
                cp_async16(dst + (uint32_t)(row * 264 + scol) * 4u, src + row * CN + scol);
            }
            cp_commit();
            cp_wait<1>();
        } else {
            cp_wait<0>();
        }
        __syncthreads();

        uint32_t hb = (uint32_t)(ch & 1) * KF_HBUF;
#pragma unroll
        for (int kk = 0; kk < 2; ++kk) {
            uint32_t kofs = (uint32_t)(16 * ch + 8 * kk) * 4u;
            uint32_t a[4][4], bb[4][2];
#pragma unroll
            for (int mt = 0; mt < 4; ++mt) {
                uint32_t ab = baseA0 + (uint32_t)mt * 14592u + kofs;
                a[mt][0] = lds32(ab);            // (o0+r,   k+cq)
                a[mt][1] = lds32(ab + 7296u);    // (o0+r+8, k+cq)
                a[mt][2] = lds32(ab + 16u);      // (o0+r,   k+cq+4)
                a[mt][3] = lds32(ab + 7312u);    // (o0+r+8, k+cq+4)
            }
#pragma unroll
            for (int nt = 0; nt < 4; ++nt) {
                uint32_t bx = baseB0 + hb + (uint32_t)nt * 32u + (uint32_t)kk * 8448u;
                bb[nt][0] = lds32(bx);
                bb[nt][1] = lds32(bx + 4224u);   // fc + 4
            }
#pragma unroll
            for (int mt = 0; mt < 4; ++mt)
#pragma unroll
                for (int nt = 0; nt < 4; ++nt)
                    mma_tf32(acc[mt][nt], a[mt], bb[nt][0], bb[nt][1]);
        }
        __syncthreads();
    }

    // epilogue: y[((b*64+o)*256+c)*64 + m]
#pragma unroll
    for (int mt = 0; mt < 4; ++mt)
#pragma unroll
        for (int nt = 0; nt < 4; ++nt) {
            int o0 = 16 * mt + r;
            int c0 = 32 * w + 8 * nt + 2 * cq;
            y[((size_t)(b * C_OUT + o0) * CN + c0) * M_ + m]         = acc[mt][nt][0] + bv[mt][0];
            y[((size_t)(b * C_OUT + o0) * CN + c0 + 1) * M_ + m]     = acc[mt][nt][1] + bv[mt][0];
            y[((size_t)(b * C_OUT + o0 + 8) * CN + c0) * M_ + m]     = acc[mt][nt][2] + bv[mt][1];
            y[((size_t)(b * C_OUT + o0 + 8) * CN + c0 + 1) * M_ + m] = acc[mt][nt][3] + bv[mt][1];
        }
}

// ================= launch =================
extern "C" void kernel_launch(void* const* d_in, const int* in_sizes, int n_in,
                              void* d_out, int out_size) {
    const float* x    = (const float*)d_in[0];
    const float* b0   = (const float*)d_in[1];
    const float* b1   = (const float*)d_in[2];
    const float* b2   = (const float*)d_in[3];
    const float* W    = (const float*)d_in[4];
    const float* bias = (const float*)d_in[5];
    float* y = (float*)d_out;

    cudaFuncSetAttribute(k_nconv, cudaFuncAttributeMaxDynamicSharedMemorySize, (int)SM_TOT);
    cudaFuncSetAttribute(k_final, cudaFuncAttributeMaxDynamicSharedMemorySize, (int)KF_TOT);

    k_transpose<<<2048, 256>>>(x);
    k_nconv<<<1536, 256, SM_TOT>>>(b0, b1, b2);
    k_final<<<512, 256, KF_TOT>>>(W, bias, y);
}

// round 13
// speedup vs baseline: 1.5796x; 1.2254x over previous
#include <cuda_runtime.h>
#include <cstdint>

#define B_    8
#define F_IN  32
#define CN    256
#define M_    64
#define C_OUT 64
#define C_CAT 224   // (2*3+1)*32

// Scratch: H[b][m][fc][c], fc in [0,224): piece p at fc=32p.
// All pieces stored pre-rounded to tf32 (fp32 bits with low mantissa zeroed).
__device__ float g_H[(size_t)B_ * M_ * C_CAT * CN];

// ================= helpers =================
__device__ __forceinline__ uint32_t smem_u32(const void* p) {
    uint32_t a;
    asm("{ .reg .u64 t; cvta.to.shared.u64 t, %1; cvt.u32.u64 %0, t; }" : "=r"(a) : "l"(p));
    return a;
}
__device__ __forceinline__ void cp_async16(uint32_t sa, const void* g) {
    asm volatile("cp.async.cg.shared.global [%0], [%1], 16;\n" :: "r"(sa), "l"(g));
}
__device__ __forceinline__ void cp_async16_pol(uint32_t sa, const void* g, uint64_t pol) {
    asm volatile("cp.async.cg.shared.global.L2::cache_hint [%0], [%1], 16, %2;\n"
                 :: "r"(sa), "l"(g), "l"(pol));
}
__device__ __forceinline__ void cp_commit() { asm volatile("cp.async.commit_group;\n"); }
template<int N> __device__ __forceinline__ void cp_wait() {
    asm volatile("cp.async.wait_group %0;\n" :: "n"(N));
}
__device__ __forceinline__ uint32_t f2tf32(float f) {
    uint32_t u; asm("cvt.rna.tf32.f32 %0, %1;" : "=r"(u) : "f"(f)); return u;
}
__device__ __forceinline__ uint32_t lds32(uint32_t a) {
    uint32_t v; asm("ld.shared.b32 %0, [%1];" : "=r"(v) : "r"(a)); return v;
}
// eviction policy: keep A slabs resident in L2 for the hop-2 re-read
__device__ __forceinline__ uint64_t mk_policy_evict_last() {
    uint64_t pol;
    asm("createpolicy.fractional.L2::evict_last.b64 %0, 1.0;" : "=l"(pol));
    return pol;
}
// mma m16n8k8 row.col tf32 -> f32
__device__ __forceinline__ void mma_tf32(float c[4], const uint32_t a[4],
                                         uint32_t b0, uint32_t b1) {
    asm volatile("mma.sync.aligned.m16n8k8.row.col.f32.tf32.tf32.f32 "
                 "{%0,%1,%2,%3},{%4,%5,%6,%7},{%8,%9},{%0,%1,%2,%3};"
                 : "+f"(c[0]), "+f"(c[1]), "+f"(c[2]), "+f"(c[3])
                 : "r"(a[0]), "r"(a[1]), "r"(a[2]), "r"(a[3]), "r"(b0), "r"(b1));
}

// ================= Kernel 1: x[b,f,n,m] -> H piece0 [b][m][f][n], tf32-rounded =================
__global__ __launch_bounds__(256) void k_transpose(const float* __restrict__ x) {
    int id = blockIdx.x;           // ((b*32 + f)*8 + nt)
    int nt = id & 7;
    int f  = (id >> 3) & 31;
    int b  = id >> 8;

    __shared__ float ts[32][65];
    int t  = threadIdx.x;
    int m  = t & 63;
    int nl = t >> 6;               // 0..3
    const float* xp = x + ((size_t)(b * F_IN + f) * CN + nt * 32) * M_;
#pragma unroll
    for (int i = 0; i < 8; ++i) {
        int r = nl + 4 * i;
        ts[r][m] = xp[(size_t)r * M_ + m];
    }
    __syncthreads();
    int nl2 = t & 31;
    int mg  = t >> 5;              // 0..7
#pragma unroll
    for (int i = 0; i < 8; ++i) {
        int mm = mg + 8 * i;
        __stcs(&g_H[((size_t)(b * M_ + mm) * C_CAT + f) * CN + nt * 32 + nl2],
               __uint_as_float(f2tf32(ts[nl2][mm])));
    }
}

// ================= Kernel 2: tf32 MMA fused double-hop nconv =================
// One CTA per (base, b, m). D[v(256) x f(32)] = sum_n A[n][v] * x[f][n]
// cp.async 16n-chunk, 4 buffers, depth-3 in flight; tf32 cvt in fragment path.
//
// smem: xs[f=32][n stride 260] fp32(tf32 bits) = 33,280 B
//       As: 4 x [n=16][v stride 264] fp32 staging = 4 x 16,896 B
//       x1s fp32 [256][33] = 33,792 B aliases As bufs 2,3
#define SM_XS  0u
#define SM_AS  33280u
#define AS_BUF 16896u
#define SM_X1  (SM_AS + 2u * AS_BUF)
#define SM_TOT (SM_AS + 4u * AS_BUF)   // 100,864 B -> occupancy 2

__device__ __forceinline__ void stage_chunk(const float* __restrict__ Ag, uint64_t pol,
                                            uint32_t sb, int rowg, int col4,
                                            int gc, int buf) {
    const float* src = Ag + (size_t)(gc * 16) * CN;
    uint32_t dst = sb + SM_AS + (uint32_t)buf * AS_BUF;
#pragma unroll
    for (int k = 0; k < 4; ++k) {
        int row = rowg + 4 * k;
        cp_async16_pol(dst + (uint32_t)(row * 264 + col4) * 4u, src + row * CN + col4, pol);
    }
}

__global__ __launch_bounds__(256, 2) void k_nconv(const float* __restrict__ b0,
                                                  const float* __restrict__ b1,
                                                  const float* __restrict__ b2)
{
    extern __shared__ char smem[];
    uint32_t sb = smem_u32(smem);
    int t   = threadIdx.x;
    int wid = t >> 5;
    int l   = t & 31;
    int r   = l >> 2;               // groupID
    int cq  = l & 3;                // threadID_in_group

    int id = blockIdx.x;            // 0..1535
    int kb = id >> 9;
    int bm = id & 511;
    const float* Ag = (kb == 0 ? b0 : (kb == 1 ? b1 : b2)) + (size_t)bm * (CN * CN);
    float* Hbm = g_H + (size_t)bm * (C_CAT * CN);

    uint64_t pol = mk_policy_evict_last();

    int rowg = t >> 6;              // 0..3
    int col4 = (t & 63) * 4;        // word col

    // ---- prologue: stage chunks 0,1,2 ----
    stage_chunk(Ag, pol, sb, rowg, col4, 0, 0); cp_commit();
    stage_chunk(Ag, pol, sb, rowg, col4, 1, 1); cp_commit();

    // xs copy from piece0 (already tf32 bits — no cvt)
    {
        uint32_t* xsw = (uint32_t*)(smem + SM_XS);
        const uint32_t* src = (const uint32_t*)Hbm;
#pragma unroll
        for (int k = 0; k < 32; ++k) {
            int idx = t + 256 * k;
            int f = idx >> 8, n = idx & 255;
            xsw[f * 260 + n] = src[idx];
        }
    }
    stage_chunk(Ag, pol, sb, rowg, col4, 2, 2); cp_commit();

    // per-lane fragment base addresses
    // A: a0 = As[n=8ks+cq][v=32wid+16mt+r]; word = (8ks+cq)*264 + v
    uint32_t baseA0 = (uint32_t)(cq * 264 + 32 * wid + r) * 4u;            // buffer-local
    // B: b0 = xs[f=8nt+r][n]; word = f*260 + n
    uint32_t baseB0 = sb + SM_XS + (uint32_t)(r * 260 + cq) * 4u;          // +8320B per nt

    float acc[2][4][4];
#pragma unroll
    for (int mt = 0; mt < 2; ++mt)
#pragma unroll
        for (int nt = 0; nt < 4; ++nt)
#pragma unroll
            for (int e = 0; e < 4; ++e) acc[mt][nt][e] = 0.0f;

    for (int it = 0; it < 32; ++it) {
        // wait for chunk 'it' (tail iterations need tighter waits)
        if (it < 30)       cp_wait<2>();
        else if (it == 30) cp_wait<1>();
        else               cp_wait<0>();
        __syncthreads();

        // issue chunk it+3 (skip at it==15: its buffer is needed for x1s; reissued at boundary)
        if (it <= 14 || (it >= 16 && it <= 28)) {
            stage_chunk(Ag, pol, sb, rowg, col4, (it + 3) & 15, (it + 3) & 3);
            cp_commit();
        }

        // ---- MMA on buf it&3, n-base = 16*(it&15) ----
        {
            uint32_t abase = sb + SM_AS + (uint32_t)(it & 3) * AS_BUF + baseA0;
            uint32_t nb4   = (uint32_t)(16 * (it & 15)) * 4u;
#pragma unroll
            for (int ks = 0; ks < 2; ++ks) {
                uint32_t a0[2][4], bb[4][2];
#pragma unroll
                for (int mt = 0; mt < 2; ++mt) {
                    uint32_t ab = abase + (uint32_t)mt * 64u + (uint32_t)ks * 8448u;
                    a0[mt][0] = f2tf32(__uint_as_float(lds32(ab)));
                    a0[mt][1] = f2tf32(__uint_as_float(lds32(ab + 32u)));
                    a0[mt][2] = f2tf32(__uint_as_float(lds32(ab + 4224u)));
                    a0[mt][3] = f2tf32(__uint_as_float(lds32(ab + 4256u)));
                }
#pragma unroll
                for (int nt = 0; nt < 4; ++nt) {
                    uint32_t bx = baseB0 + (uint32_t)nt * 8320u + nb4 + (uint32_t)ks * 32u;
                    bb[nt][0] = lds32(bx);
                    bb[nt][1] = lds32(bx + 16u);
                }
#pragma unroll
                for (int mt = 0; mt < 2; ++mt)
#pragma unroll
                    for (int nt = 0; nt < 4; ++nt)
                        mma_tf32(acc[mt][nt], a0[mt], bb[nt][0], bb[nt][1]);
            }
        }

        // ---- hop boundary after iter 15 ----
        if (it == 15) {
            __syncthreads();   // all MMA(15) reads done; bufs 2,3 free for x1s
            float* Hp  = Hbm + (size_t)(32 * (1 + 2 * kb)) * CN;
            float* x1s = (float*)(smem + SM_X1);
#pragma unroll
            for (int mt = 0; mt < 2; ++mt)
#pragma unroll
                for (int nt = 0; nt < 4; ++nt) {
                    int v0 = 32 * wid + 16 * mt + r;
                    int f0 = 8 * nt + 2 * cq;
                    float a0 = acc[mt][nt][0], a1 = acc[mt][nt][1];
                    float a2 = acc[mt][nt][2], a3 = acc[mt][nt][3];
                    __stcs(&Hp[(size_t)f0 * CN + v0],           __uint_as_float(f2tf32(a0)));
                    __stcs(&Hp[(size_t)(f0 + 1) * CN + v0],     __uint_as_float(f2tf32(a1)));
                    __stcs(&Hp[(size_t)f0 * CN + v0 + 8],       __uint_as_float(f2tf32(a2)));
                    __stcs(&Hp[(size_t)(f0 + 1) * CN + v0 + 8], __uint_as_float(f2tf32(a3)));
                    x1s[v0 * 33 + f0]           = a0;
                    x1s[v0 * 33 + f0 + 1]       = a1;
                    x1s[(v0 + 8) * 33 + f0]     = a2;
                    x1s[(v0 + 8) * 33 + f0 + 1] = a3;
                    acc[mt][nt][0] = acc[mt][nt][1] = acc[mt][nt][2] = acc[mt][nt][3] = 0.0f;
                }
            __syncthreads();
            // rebuild xs[f][n] <- tf32(x1s[n][f])
            {
                uint32_t* xsw = (uint32_t*)(smem + SM_XS);
                const float* x1r = (const float*)(smem + SM_X1);
                int f = l;
#pragma unroll
                for (int k = 0; k < 32; ++k) {
                    int n = wid + 8 * k;
                    xsw[f * 260 + n] = f2tf32(x1r[n * 33 + f]);
                }
            }
            __syncthreads();   // x1s reads complete before buf 2 is overwritten
            // reissue chunk 18 (A-chunk 2) into buf 2
            stage_chunk(Ag, pol, sb, rowg, col4, 2, 2);
            cp_commit();
        }
    }

    // ---- hop2 epilogue ----
    {
        float* Hp = Hbm + (size_t)(32 * (2 + 2 * kb)) * CN;
#pragma unroll
        for (int mt = 0; mt < 2; ++mt)
#pragma unroll
            for (int nt = 0; nt < 4; ++nt) {
                int v0 = 32 * wid + 16 * mt + r;
                int f0 = 8 * nt + 2 * cq;
                __stcs(&Hp[(size_t)f0 * CN + v0],           __uint_as_float(f2tf32(acc[mt][nt][0])));
                __stcs(&Hp[(size_t)(f0 + 1) * CN + v0],     __uint_as_float(f2tf32(acc[mt][nt][1])));
                __stcs(&Hp[(size_t)f0 * CN + v0 + 8],       __uint_as_float(f2tf32(acc[mt][nt][2])));
                __stcs(&Hp[(size_t)(f0 + 1) * CN + v0 + 8], __uint_as_float(f2tf32(acc[mt][nt][3])));
            }
    }
}

// ================= Kernel 3: tf32 MMA channel-mix =================
// One CTA per (b,m): y[o=64][c=256] = W[o][fc=224] * H[fc][c] + bias[o]
// 3 H buffers, depth-2 in flight.
#define KF_WS   0u          // Ws[o=64][fc: stride 228] tf32 -> 58368 B
#define KF_HS   58368u      // 3 x [fc=16][c: stride 264] fp32(tf32 bits)
#define KF_HBUF 16896u
#define KF_TOT  (58368u + 3u * 16896u)   // 109,056 B -> occupancy 2

__global__ __launch_bounds__(256, 2) void k_final(const float* __restrict__ W,
                                                  const float* __restrict__ bias,
                                                  float* __restrict__ y)
{
    extern __shared__ char smem[];
    uint32_t sb = smem_u32(smem);
    int t  = threadIdx.x;
    int w  = t >> 5;
    int l  = t & 31;
    int r  = l >> 2;
    int cq = l & 3;

    int bm = blockIdx.x;
    int b  = bm >> 6;
    int m  = bm & 63;
    const float* Hbm = g_H + (size_t)bm * (C_CAT * CN);

    int srow = t >> 6;          // 0..3
    int scol = (t & 63) * 4;    // word col

    // prologue: stage H chunks 0,1
#pragma unroll
    for (int k = 0; k < 4; ++k) {
        int row = srow + 4 * k;
        cp_async16(sb + KF_HS + (uint32_t)(row * 264 + scol) * 4u, Hbm + row * CN + scol);
    }
    cp_commit();
#pragma unroll
    for (int k = 0; k < 4; ++k) {
        int row = srow + 4 * k;
        cp_async16(sb + KF_HS + KF_HBUF + (uint32_t)(row * 264 + scol) * 4u,
                   Hbm + (size_t)(16 + row) * CN + scol);
    }
    cp_commit();

    // build Ws (tf32)
    {
        uint32_t* wsw = (uint32_t*)(smem + KF_WS);
        for (int i = t; i < C_OUT * C_CAT; i += 256) {
            int o = i / C_CAT, fc = i % C_CAT;
            wsw[o * 228 + fc] = f2tf32(W[i]);
        }
    }
    float bv[4][2];
#pragma unroll
    for (int mt = 0; mt < 4; ++mt) {
        bv[mt][0] = bias[16 * mt + r];
        bv[mt][1] = bias[16 * mt + r + 8];
    }

    float acc[4][4][4];
#pragma unroll
    for (int mt = 0; mt < 4; ++mt)
#pragma unroll
        for (int nt = 0; nt < 4; ++nt)
#pragma unroll
            for (int e = 0; e < 4; ++e) acc[mt][nt][e] = 0.0f;

    uint32_t baseA0 = sb + KF_WS + (uint32_t)(r * 228 + cq) * 4u;          // +14592B per mt
    uint32_t baseB0 = sb + KF_HS + (uint32_t)(cq * 264 + 32 * w + r) * 4u; // +32B per nt

    for (int ch = 0; ch < 14; ++ch) {
        if (ch < 13) cp_wait<1>(); else cp_wait<0>();
        __syncthreads();

        if (ch + 2 < 14) {
            uint32_t dst = sb + KF_HS + (uint32_t)((ch + 2) % 3) * KF_HBUF;
            const float* src = Hbm + (size_t)(16 * (ch + 2)) * CN;
#pragma unroll
            for (int k = 0; k < 4; ++k) {
                int row = srow + 4 * k;
                cp_async16(dst + (uint32_t)(row * 264 + scol) * 4u, src + row * CN + scol);
            }
            cp_commit();
        }

        uint32_t hb = (uint32_t)(ch % 3) * KF_HBUF;
#pragma unroll
        for (int kk = 0; kk < 2; ++kk) {
            uint32_t kofs = (uint32_t)(16 * ch + 8 * kk) * 4u;
            uint32_t a[4][4], bb[4][2];
#pragma unroll
            for (int mt = 0; mt < 4; ++mt) {
                uint32_t ab = baseA0 + (uint32_t)mt * 14592u + kofs;
                a[mt][0] = lds32(ab);            // (o0+r,   k+cq)
                a[mt][1] = lds32(ab + 7296u);    // (o0+r+8, k+cq)
                a[mt][2] = lds32(ab + 16u);      // (o0+r,   k+cq+4)
                a[mt][3] = lds32(ab + 7312u);    // (o0+r+8, k+cq+4)
            }
#pragma unroll
            for (int nt = 0; nt < 4; ++nt) {
                uint32_t bx = baseB0 + hb + (uint32_t)nt * 32u + (uint32_t)kk * 8448u;
                bb[nt][0] = lds32(bx);
                bb[nt][1] = lds32(bx + 4224u);   // fc + 4
            }
#pragma unroll
            for (int mt = 0; mt < 4; ++mt)
#pragma unroll
                for (int nt = 0; nt < 4; ++nt)
                    mma_tf32(acc[mt][nt], a[mt], bb[nt][0], bb[nt][1]);
        }
    }

    // epilogue: y[((b*64+o)*256+c)*64 + m]
#pragma unroll
    for (int mt = 0; mt < 4; ++mt)
#pragma unroll
        for (int nt = 0; nt < 4; ++nt) {
            int o0 = 16 * mt + r;
            int c0 = 32 * w + 8 * nt + 2 * cq;
            y[((size_t)(b * C_OUT + o0) * CN + c0) * M_ + m]         = acc[mt][nt][0] + bv[mt][0];
            y[((size_t)(b * C_OUT + o0) * CN + c0 + 1) * M_ + m]     = acc[mt][nt][1] + bv[mt][0];
            y[((size_t)(b * C_OUT + o0 + 8) * CN + c0) * M_ + m]     = acc[mt][nt][2] + bv[mt][1];
            y[((size_t)(b * C_OUT + o0 + 8) * CN + c0 + 1) * M_ + m] = acc[mt][nt][3] + bv[mt][1];
        }
}

// ================= launch =================
extern "C" void kernel_launch(void* const* d_in, const int* in_sizes, int n_in,
                              void* d_out, int out_size) {
    const float* x    = (const float*)d_in[0];
    const float* b0   = (const float*)d_in[1];
    const float* b1   = (const float*)d_in[2];
    const float* b2   = (const float*)d_in[3];
    const float* W    = (const float*)d_in[4];
    const float* bias = (const float*)d_in[5];
    float* y = (float*)d_out;

    cudaFuncSetAttribute(k_nconv, cudaFuncAttributeMaxDynamicSharedMemorySize, (int)SM_TOT);
    cudaFuncSetAttribute(k_final, cudaFuncAttributeMaxDynamicSharedMemorySize, (int)KF_TOT);

    k_transpose<<<2048, 256>>>(x);
    k_nconv<<<1536, 256, SM_TOT>>>(b0, b1, b2);
    k_final<<<512, 256, KF_TOT>>>(W, bias, y);
}